// round 13
// baseline (speedup 1.0000x reference)
#include <cuda_runtime.h>
#include <cuda_fp16.h>
#include <cstdint>

// ---------------- problem constants ----------------
#define L_TOT  9291
#define LP     9344          // 146*64
#define NT     146           // 64-row/64-col tiles
#define NI     73            // k-iterations per K-half
#define NSTEPS 256
#define STAGES 5
#define STAGE_BYTES 20480    // 2x8KB A + 2x2KB B
#define CC     7             // cached k-columns per CTA (read-once, 16KB each)
#define CACHE_OFF (STAGES * STAGE_BYTES)          // 102400
#define SD_OFF    (CACHE_OFF + CC * 16384)        // 217088
#define MB_OFF    (SD_OFF + 8704)                 // 225792
#define SCALE      16384.0f
#define INV_SCALE  (1.0f/16384.0f)

// ---------------- device scratch ----------------
__device__ __align__(16) __half d_Er[(size_t)NT * NT * 4096];  // repacked scaled (A-I), fp16, swizzled tiles
__device__ __align__(16) float  d_Th[LP * 16];                 // fp32 master state (init + final only)
__device__ __align__(16) __half d_Thh[2][NT * 1024];           // fp16 shadow state, swizzled tiles, ping-pong
__device__ __align__(16) float  d_bvec[LP];
__device__ unsigned int g_bar;                                 // global step-completion counter

// ---------------- PTX helpers ----------------
__device__ __forceinline__ void mbar_init(uint32_t a, uint32_t cnt) {
    asm volatile("mbarrier.init.shared.b64 [%0], %1;" :: "r"(a), "r"(cnt) : "memory");
}
__device__ __forceinline__ void mbar_arrive(uint32_t a) {
    asm volatile("mbarrier.arrive.shared.b64 _, [%0];" :: "r"(a) : "memory");
}
__device__ __forceinline__ void mbar_expect_tx(uint32_t a, uint32_t bytes) {
    asm volatile("mbarrier.arrive.expect_tx.shared.b64 _, [%0], %1;" :: "r"(a), "r"(bytes) : "memory");
}
__device__ __forceinline__ void mbar_wait(uint32_t a, uint32_t parity) {
    asm volatile(
        "{\n\t.reg .pred P;\n"
        "W%=:\n\tmbarrier.try_wait.parity.acquire.cta.shared::cta.b64 P, [%0], %1, 0x989680;\n"
        "\t@P bra D%=;\n\tbra W%=;\nD%=:\n\t}"
        :: "r"(a), "r"(parity) : "memory");
}
__device__ __forceinline__ void bulk_ld(uint32_t dst, const void* src, uint32_t bytes, uint32_t mb) {
    asm volatile("cp.async.bulk.shared::cluster.global.mbarrier::complete_tx::bytes [%0], [%1], %2, [%3];"
                 :: "r"(dst), "l"(src), "r"(bytes), "r"(mb) : "memory");
}
__device__ __forceinline__ void bulk_ld_mc(uint32_t dst, const void* src, uint32_t bytes, uint32_t mb, uint16_t mask) {
    asm volatile("cp.async.bulk.shared::cluster.global.mbarrier::complete_tx::bytes.multicast::cluster "
                 "[%0], [%1], %2, [%3], %4;"
                 :: "r"(dst), "l"(src), "r"(bytes), "r"(mb), "h"(mask) : "memory");
}
__device__ __forceinline__ void remote_arrive_rank0(uint32_t local_addr) {
    asm volatile(
        "{\n\t.reg .b32 ra;\n"
        "\tmapa.shared::cluster.u32 ra, %0, %1;\n"
        "\tmbarrier.arrive.shared::cluster.b64 _, [ra];\n\t}"
        :: "r"(local_addr), "r"(0) : "memory");
}
__device__ __forceinline__ uint32_t ctarank() {
    uint32_t r; asm("mov.u32 %0, %%cluster_ctarank;" : "=r"(r)); return r;
}
#define CLUSTER_SYNC_() do { \
    asm volatile("barrier.cluster.arrive.aligned;" ::: "memory"); \
    asm volatile("barrier.cluster.wait.aligned;" ::: "memory"); } while (0)

__device__ __forceinline__ void ldmatrix_x4(uint32_t& r0, uint32_t& r1, uint32_t& r2, uint32_t& r3, uint32_t addr) {
    asm volatile("ldmatrix.sync.aligned.m8n8.x4.shared.b16 {%0,%1,%2,%3}, [%4];"
                 : "=r"(r0), "=r"(r1), "=r"(r2), "=r"(r3) : "r"(addr));
}
__device__ __forceinline__ void ldmatrix_x2(uint32_t& r0, uint32_t& r1, uint32_t addr) {
    asm volatile("ldmatrix.sync.aligned.m8n8.x2.shared.b16 {%0,%1}, [%2];"
                 : "=r"(r0), "=r"(r1) : "r"(addr));
}
__device__ __forceinline__ void mma16816(float* c, uint32_t a0, uint32_t a1, uint32_t a2, uint32_t a3,
                                         uint32_t b0, uint32_t b1) {
    asm volatile("mma.sync.aligned.m16n8k16.row.col.f32.f16.f16.f32 "
                 "{%0,%1,%2,%3}, {%4,%5,%6,%7}, {%8,%9}, {%0,%1,%2,%3};"
                 : "+f"(c[0]), "+f"(c[1]), "+f"(c[2]), "+f"(c[3])
                 : "r"(a0), "r"(a1), "r"(a2), "r"(a3), "r"(b0), "r"(b1));
}
__device__ __forceinline__ unsigned ld_acq(const unsigned* p) {
    unsigned v;
    asm volatile("ld.global.acquire.gpu.u32 %0, [%1];" : "=r"(v) : "l"(p));
    return v;
}
__device__ __forceinline__ void bar1_256() {
    asm volatile("bar.sync 1, 256;" ::: "memory");
}

// Thh tile layout: tile = (k>>6), elem = b*64 + (((k&63)>>3) ^ (b&7))*8 + (k&7)
__device__ __forceinline__ int thh_off(int k, int b) {
    int r = k & 63;
    return (k >> 6) * 1024 + b * 64 + ((((r >> 3) ^ (b & 7))) << 3) + (r & 7);
}

// ---------------- kernel 1: repack A -> scaled fp16 swizzled 64x64 tiles ----------------
__global__ void __launch_bounds__(256) repack_kernel(const float* __restrict__ A) {
    size_t id = (size_t)blockIdx.x * 256 + threadIdx.x;   // one thread per 8 halves
    if (id >= (size_t)NT * NT * 512) return;
    int c  = (int)(id & 7);
    int r  = (int)((id >> 3) & 63);
    int kt = (int)((id >> 9) % NT);
    int j  = (int)(id / ((size_t)512 * NT));
    int row  = j * 64 + r;
    int colb = kt * 64 + c * 8;
    float v[8];
#pragma unroll
    for (int e = 0; e < 8; e++) {
        int col = colb + e;
        float x = 0.f;
        if (row < L_TOT && col < L_TOT) {
            x = A[(size_t)row * L_TOT + col];
            if (row == col) x -= 1.0f;
        }
        v[e] = x * SCALE;
    }
    size_t base = ((size_t)j * NT + kt) * 4096 + r * 64 + ((c ^ (r & 7)) * 8);
    __half2* p = reinterpret_cast<__half2*>(d_Er + base);
    p[0] = __floats2half2_rn(v[0], v[1]);
    p[1] = __floats2half2_rn(v[2], v[3]);
    p[2] = __floats2half2_rn(v[4], v[5]);
    p[3] = __floats2half2_rn(v[6], v[7]);
}

// ---------------- kernel 2: init state + b vector + counter ----------------
__global__ void __launch_bounds__(256) init_kernel(const float* __restrict__ Bm,
                                                   const float* __restrict__ theta) {
    if (blockIdx.x == 0 && threadIdx.x == 0) g_bar = 0u;
    int idx = blockIdx.x * 256 + threadIdx.x;
    if (idx < LP * 16) {
        int k = idx >> 4, b = idx & 15;
        float v = (k < L_TOT) ? theta[k] : 0.f;
        d_Th[idx] = v;
        d_Thh[0][thh_off(k, b)] = __float2half(v);
        if (b == 0) d_bvec[k] = (k < L_TOT) ? Bm[k] : 0.f;
    }
}

// ---------------- kernel 3: persistent recurrence, SMEM E-cache + cluster-2 B multicast ----------------
// 146 CTAs (73 clusters of 2) x 320 threads. Warps 0-7 consumers (h/mt/kq split).
// The first CC k-columns of each CTA's E slice live in a read-once SMEM cache
// (loaded via TMA at startup); for those ki the A producer skips its bulk loads.
// Warp 8 lane 0 = A producer (free-running), warp 9 lane 0 = B producer
// (rank 0 multicasts state tiles to both cluster CTAs; rank 1 paces expect_tx).
__global__ void __launch_bounds__(320) __cluster_dims__(2, 1, 1)
persist_kernel(const float* __restrict__ xs) {
    extern __shared__ char smem[];
    const uint32_t smem_u = (uint32_t)__cvta_generic_to_shared(smem);
    float* sD0 = (float*)(smem + SD_OFF);                 // 64*17 floats (h=0)
    float* sD1 = sD0 + 64 * 17;                           // 64*17 floats (h=1)
    const uint32_t mb_full  = smem_u + MB_OFF;            // full[s]  = +s*8
    const uint32_t mb_empty = mb_full + 8 * STAGES;       // empty[s] = +s*8
    const uint32_t mb_cache = mb_empty + 8 * STAGES;      // startup cache barrier

    const int tid = threadIdx.x;
    const int wid = tid >> 5, lane = tid & 31;
    const int row0 = blockIdx.x * 64;
    const uint32_t rank = ctarank();

    if (tid == 0) {
#pragma unroll
        for (int s = 0; s < STAGES; s++) {
            mbar_init(mb_full  + s * 8, 2);                          // A + B producer arrivals
            mbar_init(mb_empty + s * 8, rank == 0 ? 16u : 8u);       // + remote arrives on rank 0
        }
        mbar_init(mb_cache, 1);
        asm volatile("fence.proxy.async.shared::cta;" ::: "memory");
    }
    __syncthreads();
    CLUSTER_SYNC_();   // peer mbarriers must be live before any multicast targets them

    if (wid < 8) {
        // ======== consumers (tid 0..255): h-half, m32 tile, k32 quarter ========
        const int h  = wid >> 2;
        const int mt = (wid >> 1) & 1;
        const int kq = wid & 1;
        const int ar  = mt * 32 + (lane & 15);
        const int arx = ar & 7;
        const int ach = lane >> 4;
        const uint32_t aOff = (uint32_t)(ar * 64) * 2 + h * 8192u;
        const int bn = lane & 7;
        const int kc = (lane >> 3) & 1;
        const uint32_t bOff = 16384u + h * 2048u + (uint32_t)bn * 128;
        const int drb = mt * 32 + (lane >> 2);
        const int dc  = (lane & 3) * 2;
        float* sDh = h ? sD1 : sD0;
        const uint32_t cacheBase = smem_u + CACHE_OFF + aOff;

        // persistent per-thread fp32 master state
        const int bb = tid & 15;
        float myTh[4], myB[4];
        int rr[4], thhIdx[4];
#pragma unroll
        for (int e = 0; e < 4; e++) {
            int idx = tid + 256 * e;
            int r = idx >> 4;
            rr[e] = r;
            int grow = row0 + r;
            myTh[e] = d_Th[grow * 16 + bb];
            myB[e]  = d_bvec[grow];
            thhIdx[e] = blockIdx.x * 1024 + bb * 64 + ((((r >> 3) ^ (bb & 7))) << 3) + (r & 7);
        }

        mbar_wait(mb_cache, 0);   // E-cache resident before first use

        int cs = 0, cq = 0;
        for (int t = 0; t < NSTEPS; t++) {
            __half* __restrict__ Thh_dst = d_Thh[(t & 1) ^ 1];
            const int dirn = t & 1;

            float acc[2][2][4];
#pragma unroll
            for (int m = 0; m < 2; m++)
#pragma unroll
                for (int n = 0; n < 2; n++)
#pragma unroll
                    for (int k = 0; k < 4; k++) acc[m][n][k] = 0.f;

            for (int i = 0; i < NI; i++) {
                mbar_wait(mb_full + cs * 8, cq);
                const int ki = dirn ? (NI - 1 - i) : i;
                const uint32_t stage = smem_u + cs * STAGE_BYTES;
                const uint32_t aBase = (ki < CC) ? (cacheBase + (uint32_t)ki * 16384u)
                                                 : (stage + aOff);
                const uint32_t bBase = stage + bOff;
#pragma unroll
                for (int kk2 = 0; kk2 < 2; kk2++) {
                    const int kk  = kq * 2 + kk2;
                    const int c   = kk * 2 + ach;
                    const int cst = c ^ arx;
                    uint32_t a0, a1, a2, a3, a4, a5, a6, a7;
                    ldmatrix_x4(a0, a1, a2, a3, aBase + (uint32_t)(cst * 16));          // rows ar
                    ldmatrix_x4(a4, a5, a6, a7, aBase + 2048u + (uint32_t)(cst * 16));  // rows ar+16
                    const int c2 = kk * 2 + kc;
                    const uint32_t bAddr0 = bBase + (uint32_t)((c2 ^ bn) * 16);
                    uint32_t b00, b01, b10, b11;
                    ldmatrix_x2(b00, b01, bAddr0);            // n 0-7
                    ldmatrix_x2(b10, b11, bAddr0 + 1024);     // n 8-15
                    mma16816(acc[0][0], a0, a1, a2, a3, b00, b01);
                    mma16816(acc[0][1], a0, a1, a2, a3, b10, b11);
                    mma16816(acc[1][0], a4, a5, a6, a7, b00, b01);
                    mma16816(acc[1][1], a4, a5, a6, a7, b10, b11);
                }
                if (lane == 0) {
                    mbar_arrive(mb_empty + cs * 8);
                    if (rank) remote_arrive_rank0(mb_empty + cs * 8);
                }
                if (++cs == STAGES) { cs = 0; cq ^= 1; }
            }

            // 4-way reduce: kq=0 writes its h-buffer, kq=1 adds
            bar1_256();
            if (kq == 0) {
#pragma unroll
                for (int m = 0; m < 2; m++) {
                    const int dr = drb + m * 16;
#pragma unroll
                    for (int n = 0; n < 2; n++) {
                        sDh[dr * 17 + n * 8 + dc]           = acc[m][n][0];
                        sDh[dr * 17 + n * 8 + dc + 1]       = acc[m][n][1];
                        sDh[(dr + 8) * 17 + n * 8 + dc]     = acc[m][n][2];
                        sDh[(dr + 8) * 17 + n * 8 + dc + 1] = acc[m][n][3];
                    }
                }
            }
            bar1_256();
            if (kq == 1) {
#pragma unroll
                for (int m = 0; m < 2; m++) {
                    const int dr = drb + m * 16;
#pragma unroll
                    for (int n = 0; n < 2; n++) {
                        sDh[dr * 17 + n * 8 + dc]           += acc[m][n][0];
                        sDh[dr * 17 + n * 8 + dc + 1]       += acc[m][n][1];
                        sDh[(dr + 8) * 17 + n * 8 + dc]     += acc[m][n][2];
                        sDh[(dr + 8) * 17 + n * 8 + dc + 1] += acc[m][n][3];
                    }
                }
            }
            bar1_256();

            // state update: registers + fp16 shadow write
            const float xv = xs[bb * NSTEPS + t];
#pragma unroll
            for (int e = 0; e < 4; e++) {
                const float d = sD0[rr[e] * 17 + bb] + sD1[rr[e] * 17 + bb];
                float val = myTh[e] + d * INV_SCALE + myB[e] * xv;
                myTh[e] = val;
                Thh_dst[thhIdx[e]] = __float2half(val);
            }
            if (t == NSTEPS - 1) {
#pragma unroll
                for (int e = 0; e < 4; e++)
                    d_Th[(row0 + rr[e]) * 16 + bb] = myTh[e];
            }

            // publish this CTA's step completion (fire-and-forget release red)
            __threadfence();
            asm volatile("fence.proxy.async.global;" ::: "memory");
            bar1_256();
            if (tid == 0)
                asm volatile("red.release.gpu.global.add.u32 [%0], %1;" :: "l"(&g_bar), "r"(1u) : "memory");
        }
    } else if (wid == 8 && lane == 0) {
        // ======== A producer: startup E-cache fill, then free-running pipeline ========
        const __half* tA = d_Er + (size_t)blockIdx.x * NT * 4096;
        // fill the read-once cache (CC columns x both halves)
        mbar_expect_tx(mb_cache, CC * 16384);
#pragma unroll
        for (int kci = 0; kci < CC; kci++) {
            const uint32_t cdst = smem_u + CACHE_OFF + kci * 16384;
            bulk_ld(cdst,        tA + (size_t)kci * 4096,        8192, mb_cache);
            bulk_ld(cdst + 8192, tA + (size_t)(73 + kci) * 4096, 8192, mb_cache);
        }
        int ps = 0, pq = 0;
        long pg = 0;
        for (int t = 0; t < NSTEPS; t++) {
            const int dirn = t & 1;
            for (int i = 0; i < NI; i++) {
                if (pg >= STAGES) mbar_wait(mb_empty + ps * 8, pq ^ 1);
                const int ki = dirn ? (NI - 1 - i) : i;
                const uint32_t fb  = mb_full + ps * 8;
                if (ki < CC) {
                    mbar_arrive(fb);            // cached column: no A bytes, just arrive
                } else {
                    const uint32_t dst = smem_u + ps * STAGE_BYTES;
                    mbar_expect_tx(fb, 16384);
                    bulk_ld(dst,        tA + (size_t)ki * 4096,        8192, fb);
                    bulk_ld(dst + 8192, tA + (size_t)(73 + ki) * 4096, 8192, fb);
                }
                pg++;
                if (++ps == STAGES) { ps = 0; pq ^= 1; }
            }
        }
    } else if (wid == 9 && lane == 0) {
        // ======== B producer: rank 0 multicasts state tiles to both cluster CTAs ========
        int ps = 0, pq = 0;
        long pg = 0;
        if (rank == 0) {
            for (int t = 0; t < NSTEPS; t++) {
                const unsigned target = (unsigned)NT * (unsigned)t;
                if (t) {
                    unsigned v = ld_acq(&g_bar);
                    while (v < target) { __nanosleep(32); v = ld_acq(&g_bar); }
                }
                const __half* __restrict__ Thh_src = d_Thh[t & 1];
                const int dirn = t & 1;
                for (int i = 0; i < NI; i++) {
                    if (pg >= STAGES) mbar_wait(mb_empty + ps * 8, pq ^ 1);  // both CTAs empty
                    const int ki = dirn ? (NI - 1 - i) : i;
                    const uint32_t fb  = mb_full + ps * 8;
                    const uint32_t dst = smem_u + ps * STAGE_BYTES;
                    mbar_expect_tx(fb, 4096);
                    bulk_ld_mc(dst + 16384, Thh_src + (size_t)ki * 1024,        2048, fb, 0x3);
                    bulk_ld_mc(dst + 18432, Thh_src + (size_t)(73 + ki) * 1024, 2048, fb, 0x3);
                    pg++;
                    if (++ps == STAGES) { ps = 0; pq ^= 1; }
                }
            }
        } else {
            // pacing-only: keep expect_tx in phase; data+tx arrive via rank 0's multicast
            for (int t = 0; t < NSTEPS; t++) {
                for (int i = 0; i < NI; i++) {
                    if (pg >= STAGES) mbar_wait(mb_empty + ps * 8, pq ^ 1);
                    mbar_expect_tx(mb_full + ps * 8, 4096);
                    pg++;
                    if (++ps == STAGES) { ps = 0; pq ^= 1; }
                }
            }
        }
    }

    // no CTA may exit while peer multicast could still target its smem
    CLUSTER_SYNC_();
}

// ---------------- kernel 4: MLP epilogue ----------------
__global__ void __launch_bounds__(256) mlp_kernel(float* __restrict__ out) {
    __shared__ float sW1r[64], sb1r[64], sW2r[64 * 64], sb2r[64], sW3r[64], sb3r[1];
    __shared__ float sW1c[64], sb1c[64], sW2c[64 * 64], sb2c[64], sW3c[64 * 10], sb3c[10];
    __shared__ float sh1[4][64];
    __shared__ float sred[4][2][10];

    const int b  = blockIdx.x;
    const int t0 = blockIdx.y * 16;
    const float* __restrict__ Th = d_Th;

    for (int k = threadIdx.x; k < L_TOT; k += 256) {
        float v = Th[k * 16 + b];
        if      (k < 64)   sW1r[k] = v;
        else if (k < 128)  sb1r[k - 64] = v;
        else if (k < 4224) { int o = (k - 128) >> 6, in = (k - 128) & 63; sW2r[in * 64 + o] = v; }
        else if (k < 4288) sb2r[k - 4224] = v;
        else if (k < 4352) sW3r[k - 4288] = v;
        else if (k < 4353) sb3r[0] = v;
        else if (k < 4417) sW1c[k - 4353] = v;
        else if (k < 4481) sb1c[k - 4417] = v;
        else if (k < 8577) { int o = (k - 4481) >> 6, in = (k - 4481) & 63; sW2c[in * 64 + o] = v; }
        else if (k < 8641) sb2c[k - 8577] = v;
        else if (k < 9281) { int o = (k - 8641) >> 6, in = (k - 8641) & 63; sW3c[in * 10 + o] = v; }
        else               sb3c[k - 9281] = v;
    }
    __syncthreads();

    const int g = threadIdx.x >> 6, i = threadIdx.x & 63;
    const int wing = (threadIdx.x >> 5) & 1, lane = threadIdx.x & 31;

    for (int tl = 0; tl < 4; tl++) {
        const int t = t0 + tl * 4 + g;
        const float ts = (float)t * (1.0f / 255.0f);

        float h1 = fmaxf(fmaf(sW1r[i], ts, sb1r[i]), 0.f);
        sh1[g][i] = h1;
        __syncthreads();
        float a2 = sb2r[i];
#pragma unroll
        for (int j = 0; j < 64; j++) a2 = fmaf(sW2r[j * 64 + i], sh1[g][j], a2);
        float h2 = fmaxf(a2, 0.f);
        float v = sW3r[i] * h2;
#pragma unroll
        for (int off = 16; off > 0; off >>= 1) v += __shfl_down_sync(0xffffffffu, v, off);
        if (lane == 0) sred[g][wing][0] = v;
        __syncthreads();
        if (i == 0) out[b * 256 + t] = sred[g][0][0] + sred[g][1][0] + sb3r[0];
        __syncthreads();

        float h1c = fmaxf(fmaf(sW1c[i], ts, sb1c[i]), 0.f);
        sh1[g][i] = h1c;
        __syncthreads();
        float a2c = sb2c[i];
#pragma unroll
        for (int j = 0; j < 64; j++) a2c = fmaf(sW2c[j * 64 + i], sh1[g][j], a2c);
        float h2c = fmaxf(a2c, 0.f);
        float vo[10];
#pragma unroll
        for (int o = 0; o < 10; o++) vo[o] = sW3c[i * 10 + o] * h2c;
#pragma unroll
        for (int off = 16; off > 0; off >>= 1)
#pragma unroll
            for (int o = 0; o < 10; o++) vo[o] += __shfl_down_sync(0xffffffffu, vo[o], off);
        if (lane == 0)
#pragma unroll
            for (int o = 0; o < 10; o++) sred[g][wing][o] = vo[o];
        __syncthreads();
        if (i < 10) out[4096 + (b * 256 + t) * 10 + i] = sred[g][0][i] + sred[g][1][i] + sb3c[i];
        __syncthreads();
    }
}

// ---------------- host launch ----------------
extern "C" void kernel_launch(void* const* d_in, const int* in_sizes, int n_in,
                              void* d_out, int out_size) {
    const float* xs    = (const float*)d_in[0];
    const float* A     = (const float*)d_in[1];
    const float* Bm    = (const float*)d_in[2];
    const float* theta = (const float*)d_in[3];
    float* out = (float*)d_out;

    constexpr int SMEM_BYTES = MB_OFF + 8 * STAGES * 2 + 16 + 48;  // 225936
    cudaFuncSetAttribute(persist_kernel, cudaFuncAttributeMaxDynamicSharedMemorySize, SMEM_BYTES);

    repack_kernel<<<2 * NT * NT, 256>>>(A);
    init_kernel<<<(LP * 16 + 255) / 256, 256>>>(Bm, theta);
    persist_kernel<<<NT, 320, SMEM_BYTES>>>(xs);   // __cluster_dims__(2,1,1) applies
    mlp_kernel<<<dim3(16, 16), 256>>>(out);
}

// round 14
// speedup vs baseline: 1.0247x; 1.0247x over previous
#include <cuda_runtime.h>
#include <cuda_fp16.h>
#include <cstdint>

// ---------------- problem constants ----------------
#define L_TOT  9291
#define LP     9344          // 146*64
#define NT     146           // 64-row/64-col tiles
#define NI     73            // k-iterations per K-half
#define NSTEPS 256
#define STAGES 6
#define STAGE_BYTES 20480    // 2x8KB A + 2x2KB B
#define CC     6             // cached k-columns per CTA (read-once, 16KB each)
#define CACHE_OFF (STAGES * STAGE_BYTES)          // 122880
#define SD_OFF    (CACHE_OFF + CC * 16384)        // 221184
#define MB_OFF    (SD_OFF + 8704)                 // 229888
#define SCALE      16384.0f
#define INV_SCALE  (1.0f/16384.0f)

// ---------------- device scratch ----------------
__device__ __align__(16) __half d_Er[(size_t)NT * NT * 4096];  // repacked scaled (A-I), fp16, swizzled tiles
__device__ __align__(16) float  d_Th[LP * 16];                 // fp32 master state (init + final only)
__device__ __align__(16) __half d_Thh[2][NT * 1024];           // fp16 shadow state, swizzled tiles, ping-pong
__device__ __align__(16) float  d_bvec[LP];
__device__ unsigned int g_bar;                                 // global step-completion counter

// ---------------- PTX helpers ----------------
__device__ __forceinline__ void mbar_init(uint32_t a, uint32_t cnt) {
    asm volatile("mbarrier.init.shared.b64 [%0], %1;" :: "r"(a), "r"(cnt) : "memory");
}
__device__ __forceinline__ void mbar_arrive(uint32_t a) {
    asm volatile("mbarrier.arrive.shared.b64 _, [%0];" :: "r"(a) : "memory");
}
__device__ __forceinline__ void mbar_expect_tx(uint32_t a, uint32_t bytes) {
    asm volatile("mbarrier.arrive.expect_tx.shared.b64 _, [%0], %1;" :: "r"(a), "r"(bytes) : "memory");
}
__device__ __forceinline__ void mbar_wait(uint32_t a, uint32_t parity) {
    asm volatile(
        "{\n\t.reg .pred P;\n"
        "W%=:\n\tmbarrier.try_wait.parity.acquire.cta.shared::cta.b64 P, [%0], %1, 0x989680;\n"
        "\t@P bra D%=;\n\tbra W%=;\nD%=:\n\t}"
        :: "r"(a), "r"(parity) : "memory");
}
__device__ __forceinline__ void bulk_ld(uint32_t dst, const void* src, uint32_t bytes, uint32_t mb) {
    asm volatile("cp.async.bulk.shared::cluster.global.mbarrier::complete_tx::bytes [%0], [%1], %2, [%3];"
                 :: "r"(dst), "l"(src), "r"(bytes), "r"(mb) : "memory");
}
__device__ __forceinline__ void bulk_ld_mc(uint32_t dst, const void* src, uint32_t bytes, uint32_t mb, uint16_t mask) {
    asm volatile("cp.async.bulk.shared::cluster.global.mbarrier::complete_tx::bytes.multicast::cluster "
                 "[%0], [%1], %2, [%3], %4;"
                 :: "r"(dst), "l"(src), "r"(bytes), "r"(mb), "h"(mask) : "memory");
}
__device__ __forceinline__ void remote_arrive_rank0(uint32_t local_addr) {
    asm volatile(
        "{\n\t.reg .b32 ra;\n"
        "\tmapa.shared::cluster.u32 ra, %0, %1;\n"
        "\tmbarrier.arrive.shared::cluster.b64 _, [ra];\n\t}"
        :: "r"(local_addr), "r"(0) : "memory");
}
__device__ __forceinline__ uint32_t ctarank() {
    uint32_t r; asm("mov.u32 %0, %%cluster_ctarank;" : "=r"(r)); return r;
}
#define CLUSTER_SYNC_() do { \
    asm volatile("barrier.cluster.arrive.aligned;" ::: "memory"); \
    asm volatile("barrier.cluster.wait.aligned;" ::: "memory"); } while (0)

__device__ __forceinline__ void ldmatrix_x4(uint32_t& r0, uint32_t& r1, uint32_t& r2, uint32_t& r3, uint32_t addr) {
    asm volatile("ldmatrix.sync.aligned.m8n8.x4.shared.b16 {%0,%1,%2,%3}, [%4];"
                 : "=r"(r0), "=r"(r1), "=r"(r2), "=r"(r3) : "r"(addr));
}
__device__ __forceinline__ void ldmatrix_x2(uint32_t& r0, uint32_t& r1, uint32_t addr) {
    asm volatile("ldmatrix.sync.aligned.m8n8.x2.shared.b16 {%0,%1}, [%2];"
                 : "=r"(r0), "=r"(r1) : "r"(addr));
}
__device__ __forceinline__ void mma16816(float* c, uint32_t a0, uint32_t a1, uint32_t a2, uint32_t a3,
                                         uint32_t b0, uint32_t b1) {
    asm volatile("mma.sync.aligned.m16n8k16.row.col.f32.f16.f16.f32 "
                 "{%0,%1,%2,%3}, {%4,%5,%6,%7}, {%8,%9}, {%0,%1,%2,%3};"
                 : "+f"(c[0]), "+f"(c[1]), "+f"(c[2]), "+f"(c[3])
                 : "r"(a0), "r"(a1), "r"(a2), "r"(a3), "r"(b0), "r"(b1));
}
__device__ __forceinline__ unsigned ld_acq(const unsigned* p) {
    unsigned v;
    asm volatile("ld.global.acquire.gpu.u32 %0, [%1];" : "=r"(v) : "l"(p));
    return v;
}
__device__ __forceinline__ void bar1_256() {
    asm volatile("bar.sync 1, 256;" ::: "memory");
}

// Thh tile layout: tile = (k>>6), elem = b*64 + (((k&63)>>3) ^ (b&7))*8 + (k&7)
__device__ __forceinline__ int thh_off(int k, int b) {
    int r = k & 63;
    return (k >> 6) * 1024 + b * 64 + ((((r >> 3) ^ (b & 7))) << 3) + (r & 7);
}

// ---------------- kernel 1: repack A -> scaled fp16 swizzled 64x64 tiles ----------------
__global__ void __launch_bounds__(256) repack_kernel(const float* __restrict__ A) {
    size_t id = (size_t)blockIdx.x * 256 + threadIdx.x;   // one thread per 8 halves
    if (id >= (size_t)NT * NT * 512) return;
    int c  = (int)(id & 7);
    int r  = (int)((id >> 3) & 63);
    int kt = (int)((id >> 9) % NT);
    int j  = (int)(id / ((size_t)512 * NT));
    int row  = j * 64 + r;
    int colb = kt * 64 + c * 8;
    float v[8];
#pragma unroll
    for (int e = 0; e < 8; e++) {
        int col = colb + e;
        float x = 0.f;
        if (row < L_TOT && col < L_TOT) {
            x = A[(size_t)row * L_TOT + col];
            if (row == col) x -= 1.0f;
        }
        v[e] = x * SCALE;
    }
    size_t base = ((size_t)j * NT + kt) * 4096 + r * 64 + ((c ^ (r & 7)) * 8);
    __half2* p = reinterpret_cast<__half2*>(d_Er + base);
    p[0] = __floats2half2_rn(v[0], v[1]);
    p[1] = __floats2half2_rn(v[2], v[3]);
    p[2] = __floats2half2_rn(v[4], v[5]);
    p[3] = __floats2half2_rn(v[6], v[7]);
}

// ---------------- kernel 2: init state + b vector + counter ----------------
__global__ void __launch_bounds__(256) init_kernel(const float* __restrict__ Bm,
                                                   const float* __restrict__ theta) {
    if (blockIdx.x == 0 && threadIdx.x == 0) g_bar = 0u;
    int idx = blockIdx.x * 256 + threadIdx.x;
    if (idx < LP * 16) {
        int k = idx >> 4, b = idx & 15;
        float v = (k < L_TOT) ? theta[k] : 0.f;
        d_Th[idx] = v;
        d_Thh[0][thh_off(k, b)] = __float2half(v);
        if (b == 0) d_bvec[k] = (k < L_TOT) ? Bm[k] : 0.f;
    }
}

// ---------------- kernel 3: persistent recurrence, SMEM E-cache + cluster-2 B multicast ----------------
// 146 CTAs (73 clusters of 2) x 320 threads. Warps 0-7 consumers (h/mt/kq split).
// The first CC k-columns of each CTA's E slice live in a read-once SMEM cache
// (loaded via TMA at startup); for those ki the A producer skips its bulk loads.
// Warp 8 lane 0 = A producer (free-running), warp 9 lane 0 = B producer
// (rank 0 multicasts state tiles to both cluster CTAs; rank 1 paces expect_tx).
__global__ void __launch_bounds__(320) __cluster_dims__(2, 1, 1)
persist_kernel(const float* __restrict__ xs) {
    extern __shared__ char smem[];
    const uint32_t smem_u = (uint32_t)__cvta_generic_to_shared(smem);
    float* sD0 = (float*)(smem + SD_OFF);                 // 64*17 floats (h=0)
    float* sD1 = sD0 + 64 * 17;                           // 64*17 floats (h=1)
    const uint32_t mb_full  = smem_u + MB_OFF;            // full[s]  = +s*8
    const uint32_t mb_empty = mb_full + 8 * STAGES;       // empty[s] = +s*8
    const uint32_t mb_cache = mb_empty + 8 * STAGES;      // startup cache barrier

    const int tid = threadIdx.x;
    const int wid = tid >> 5, lane = tid & 31;
    const int row0 = blockIdx.x * 64;
    const uint32_t rank = ctarank();

    if (tid == 0) {
#pragma unroll
        for (int s = 0; s < STAGES; s++) {
            mbar_init(mb_full  + s * 8, 2);                          // A + B producer arrivals
            mbar_init(mb_empty + s * 8, rank == 0 ? 16u : 8u);       // + remote arrives on rank 0
        }
        mbar_init(mb_cache, 1);
        asm volatile("fence.proxy.async.shared::cta;" ::: "memory");
    }
    __syncthreads();
    CLUSTER_SYNC_();   // peer mbarriers must be live before any multicast targets them

    if (wid < 8) {
        // ======== consumers (tid 0..255): h-half, m32 tile, k32 quarter ========
        const int h  = wid >> 2;
        const int mt = (wid >> 1) & 1;
        const int kq = wid & 1;
        const int ar  = mt * 32 + (lane & 15);
        const int arx = ar & 7;
        const int ach = lane >> 4;
        const uint32_t aOff = (uint32_t)(ar * 64) * 2 + h * 8192u;
        const int bn = lane & 7;
        const int kc = (lane >> 3) & 1;
        const uint32_t bOff = 16384u + h * 2048u + (uint32_t)bn * 128;
        const int drb = mt * 32 + (lane >> 2);
        const int dc  = (lane & 3) * 2;
        float* sDh = h ? sD1 : sD0;
        const uint32_t cacheBase = smem_u + CACHE_OFF + aOff;

        // persistent per-thread fp32 master state
        const int bb = tid & 15;
        float myTh[4], myB[4];
        int rr[4], thhIdx[4];
#pragma unroll
        for (int e = 0; e < 4; e++) {
            int idx = tid + 256 * e;
            int r = idx >> 4;
            rr[e] = r;
            int grow = row0 + r;
            myTh[e] = d_Th[grow * 16 + bb];
            myB[e]  = d_bvec[grow];
            thhIdx[e] = blockIdx.x * 1024 + bb * 64 + ((((r >> 3) ^ (bb & 7))) << 3) + (r & 7);
        }

        mbar_wait(mb_cache, 0);   // E-cache resident before first use

        int cs = 0, cq = 0;
        for (int t = 0; t < NSTEPS; t++) {
            __half* __restrict__ Thh_dst = d_Thh[(t & 1) ^ 1];
            const int dirn = t & 1;

            float acc[2][2][4];
#pragma unroll
            for (int m = 0; m < 2; m++)
#pragma unroll
                for (int n = 0; n < 2; n++)
#pragma unroll
                    for (int k = 0; k < 4; k++) acc[m][n][k] = 0.f;

            for (int i = 0; i < NI; i++) {
                mbar_wait(mb_full + cs * 8, cq);
                const int ki = dirn ? (NI - 1 - i) : i;
                const uint32_t stage = smem_u + cs * STAGE_BYTES;
                const uint32_t aBase = (ki < CC) ? (cacheBase + (uint32_t)ki * 16384u)
                                                 : (stage + aOff);
                const uint32_t bBase = stage + bOff;
#pragma unroll
                for (int kk2 = 0; kk2 < 2; kk2++) {
                    const int kk  = kq * 2 + kk2;
                    const int c   = kk * 2 + ach;
                    const int cst = c ^ arx;
                    uint32_t a0, a1, a2, a3, a4, a5, a6, a7;
                    ldmatrix_x4(a0, a1, a2, a3, aBase + (uint32_t)(cst * 16));          // rows ar
                    ldmatrix_x4(a4, a5, a6, a7, aBase + 2048u + (uint32_t)(cst * 16));  // rows ar+16
                    const int c2 = kk * 2 + kc;
                    const uint32_t bAddr0 = bBase + (uint32_t)((c2 ^ bn) * 16);
                    uint32_t b00, b01, b10, b11;
                    ldmatrix_x2(b00, b01, bAddr0);            // n 0-7
                    ldmatrix_x2(b10, b11, bAddr0 + 1024);     // n 8-15
                    mma16816(acc[0][0], a0, a1, a2, a3, b00, b01);
                    mma16816(acc[0][1], a0, a1, a2, a3, b10, b11);
                    mma16816(acc[1][0], a4, a5, a6, a7, b00, b01);
                    mma16816(acc[1][1], a4, a5, a6, a7, b10, b11);
                }
                if (lane == 0) {
                    mbar_arrive(mb_empty + cs * 8);
                    if (rank) remote_arrive_rank0(mb_empty + cs * 8);
                }
                if (++cs == STAGES) { cs = 0; cq ^= 1; }
            }

            // 4-way reduce: kq=0 writes its h-buffer, kq=1 adds
            bar1_256();
            if (kq == 0) {
#pragma unroll
                for (int m = 0; m < 2; m++) {
                    const int dr = drb + m * 16;
#pragma unroll
                    for (int n = 0; n < 2; n++) {
                        sDh[dr * 17 + n * 8 + dc]           = acc[m][n][0];
                        sDh[dr * 17 + n * 8 + dc + 1]       = acc[m][n][1];
                        sDh[(dr + 8) * 17 + n * 8 + dc]     = acc[m][n][2];
                        sDh[(dr + 8) * 17 + n * 8 + dc + 1] = acc[m][n][3];
                    }
                }
            }
            bar1_256();
            if (kq == 1) {
#pragma unroll
                for (int m = 0; m < 2; m++) {
                    const int dr = drb + m * 16;
#pragma unroll
                    for (int n = 0; n < 2; n++) {
                        sDh[dr * 17 + n * 8 + dc]           += acc[m][n][0];
                        sDh[dr * 17 + n * 8 + dc + 1]       += acc[m][n][1];
                        sDh[(dr + 8) * 17 + n * 8 + dc]     += acc[m][n][2];
                        sDh[(dr + 8) * 17 + n * 8 + dc + 1] += acc[m][n][3];
                    }
                }
            }
            bar1_256();

            // state update: registers + fp16 shadow write
            const float xv = xs[bb * NSTEPS + t];
#pragma unroll
            for (int e = 0; e < 4; e++) {
                const float d = sD0[rr[e] * 17 + bb] + sD1[rr[e] * 17 + bb];
                float val = myTh[e] + d * INV_SCALE + myB[e] * xv;
                myTh[e] = val;
                Thh_dst[thhIdx[e]] = __float2half(val);
            }
            if (t == NSTEPS - 1) {
#pragma unroll
                for (int e = 0; e < 4; e++)
                    d_Th[(row0 + rr[e]) * 16 + bb] = myTh[e];
            }

            // publish this CTA's step completion (fire-and-forget release red)
            __threadfence();
            asm volatile("fence.proxy.async.global;" ::: "memory");
            bar1_256();
            if (tid == 0)
                asm volatile("red.release.gpu.global.add.u32 [%0], %1;" :: "l"(&g_bar), "r"(1u) : "memory");
        }
    } else if (wid == 8 && lane == 0) {
        // ======== A producer: startup E-cache fill, then free-running pipeline ========
        const __half* tA = d_Er + (size_t)blockIdx.x * NT * 4096;
        // fill the read-once cache (CC columns x both halves)
        mbar_expect_tx(mb_cache, CC * 16384);
#pragma unroll
        for (int kci = 0; kci < CC; kci++) {
            const uint32_t cdst = smem_u + CACHE_OFF + kci * 16384;
            bulk_ld(cdst,        tA + (size_t)kci * 4096,        8192, mb_cache);
            bulk_ld(cdst + 8192, tA + (size_t)(73 + kci) * 4096, 8192, mb_cache);
        }
        int ps = 0, pq = 0;
        long pg = 0;
        for (int t = 0; t < NSTEPS; t++) {
            const int dirn = t & 1;
            for (int i = 0; i < NI; i++) {
                if (pg >= STAGES) mbar_wait(mb_empty + ps * 8, pq ^ 1);
                const int ki = dirn ? (NI - 1 - i) : i;
                const uint32_t fb  = mb_full + ps * 8;
                if (ki < CC) {
                    mbar_arrive(fb);            // cached column: no A bytes, just arrive
                } else {
                    const uint32_t dst = smem_u + ps * STAGE_BYTES;
                    mbar_expect_tx(fb, 16384);
                    bulk_ld(dst,        tA + (size_t)ki * 4096,        8192, fb);
                    bulk_ld(dst + 8192, tA + (size_t)(73 + ki) * 4096, 8192, fb);
                }
                pg++;
                if (++ps == STAGES) { ps = 0; pq ^= 1; }
            }
        }
    } else if (wid == 9 && lane == 0) {
        // ======== B producer: rank 0 multicasts state tiles to both cluster CTAs ========
        int ps = 0, pq = 0;
        long pg = 0;
        if (rank == 0) {
            for (int t = 0; t < NSTEPS; t++) {
                const unsigned target = (unsigned)NT * (unsigned)t;
                if (t) {
                    unsigned v = ld_acq(&g_bar);
                    while (v < target) { __nanosleep(32); v = ld_acq(&g_bar); }
                }
                const __half* __restrict__ Thh_src = d_Thh[t & 1];
                const int dirn = t & 1;
                for (int i = 0; i < NI; i++) {
                    if (pg >= STAGES) mbar_wait(mb_empty + ps * 8, pq ^ 1);  // both CTAs empty
                    const int ki = dirn ? (NI - 1 - i) : i;
                    const uint32_t fb  = mb_full + ps * 8;
                    const uint32_t dst = smem_u + ps * STAGE_BYTES;
                    mbar_expect_tx(fb, 4096);
                    bulk_ld_mc(dst + 16384, Thh_src + (size_t)ki * 1024,        2048, fb, 0x3);
                    bulk_ld_mc(dst + 18432, Thh_src + (size_t)(73 + ki) * 1024, 2048, fb, 0x3);
                    pg++;
                    if (++ps == STAGES) { ps = 0; pq ^= 1; }
                }
            }
        } else {
            // pacing-only: keep expect_tx in phase; data+tx arrive via rank 0's multicast
            for (int t = 0; t < NSTEPS; t++) {
                for (int i = 0; i < NI; i++) {
                    if (pg >= STAGES) mbar_wait(mb_empty + ps * 8, pq ^ 1);
                    mbar_expect_tx(mb_full + ps * 8, 4096);
                    pg++;
                    if (++ps == STAGES) { ps = 0; pq ^= 1; }
                }
            }
        }
    }

    // no CTA may exit while peer multicast could still target its smem
    CLUSTER_SYNC_();
}

// ---------------- kernel 4: MLP epilogue ----------------
__global__ void __launch_bounds__(256) mlp_kernel(float* __restrict__ out) {
    __shared__ float sW1r[64], sb1r[64], sW2r[64 * 64], sb2r[64], sW3r[64], sb3r[1];
    __shared__ float sW1c[64], sb1c[64], sW2c[64 * 64], sb2c[64], sW3c[64 * 10], sb3c[10];
    __shared__ float sh1[4][64];
    __shared__ float sred[4][2][10];

    const int b  = blockIdx.x;
    const int t0 = blockIdx.y * 16;
    const float* __restrict__ Th = d_Th;

    for (int k = threadIdx.x; k < L_TOT; k += 256) {
        float v = Th[k * 16 + b];
        if      (k < 64)   sW1r[k] = v;
        else if (k < 128)  sb1r[k - 64] = v;
        else if (k < 4224) { int o = (k - 128) >> 6, in = (k - 128) & 63; sW2r[in * 64 + o] = v; }
        else if (k < 4288) sb2r[k - 4224] = v;
        else if (k < 4352) sW3r[k - 4288] = v;
        else if (k < 4353) sb3r[0] = v;
        else if (k < 4417) sW1c[k - 4353] = v;
        else if (k < 4481) sb1c[k - 4417] = v;
        else if (k < 8577) { int o = (k - 4481) >> 6, in = (k - 4481) & 63; sW2c[in * 64 + o] = v; }
        else if (k < 8641) sb2c[k - 8577] = v;
        else if (k < 9281) { int o = (k - 8641) >> 6, in = (k - 8641) & 63; sW3c[in * 10 + o] = v; }
        else               sb3c[k - 9281] = v;
    }
    __syncthreads();

    const int g = threadIdx.x >> 6, i = threadIdx.x & 63;
    const int wing = (threadIdx.x >> 5) & 1, lane = threadIdx.x & 31;

    for (int tl = 0; tl < 4; tl++) {
        const int t = t0 + tl * 4 + g;
        const float ts = (float)t * (1.0f / 255.0f);

        float h1 = fmaxf(fmaf(sW1r[i], ts, sb1r[i]), 0.f);
        sh1[g][i] = h1;
        __syncthreads();
        float a2 = sb2r[i];
#pragma unroll
        for (int j = 0; j < 64; j++) a2 = fmaf(sW2r[j * 64 + i], sh1[g][j], a2);
        float h2 = fmaxf(a2, 0.f);
        float v = sW3r[i] * h2;
#pragma unroll
        for (int off = 16; off > 0; off >>= 1) v += __shfl_down_sync(0xffffffffu, v, off);
        if (lane == 0) sred[g][wing][0] = v;
        __syncthreads();
        if (i == 0) out[b * 256 + t] = sred[g][0][0] + sred[g][1][0] + sb3r[0];
        __syncthreads();

        float h1c = fmaxf(fmaf(sW1c[i], ts, sb1c[i]), 0.f);
        sh1[g][i] = h1c;
        __syncthreads();
        float a2c = sb2c[i];
#pragma unroll
        for (int j = 0; j < 64; j++) a2c = fmaf(sW2c[j * 64 + i], sh1[g][j], a2c);
        float h2c = fmaxf(a2c, 0.f);
        float vo[10];
#pragma unroll
        for (int o = 0; o < 10; o++) vo[o] = sW3c[i * 10 + o] * h2c;
#pragma unroll
        for (int off = 16; off > 0; off >>= 1)
#pragma unroll
            for (int o = 0; o < 10; o++) vo[o] += __shfl_down_sync(0xffffffffu, vo[o], off);
        if (lane == 0)
#pragma unroll
            for (int o = 0; o < 10; o++) sred[g][wing][o] = vo[o];
        __syncthreads();
        if (i < 10) out[4096 + (b * 256 + t) * 10 + i] = sred[g][0][i] + sred[g][1][i] + sb3c[i];
        __syncthreads();
    }
}

// ---------------- host launch ----------------
extern "C" void kernel_launch(void* const* d_in, const int* in_sizes, int n_in,
                              void* d_out, int out_size) {
    const float* xs    = (const float*)d_in[0];
    const float* A     = (const float*)d_in[1];
    const float* Bm    = (const float*)d_in[2];
    const float* theta = (const float*)d_in[3];
    float* out = (float*)d_out;

    constexpr int SMEM_BYTES = MB_OFF + 8 * STAGES * 2 + 16 + 48;  // 230048
    cudaFuncSetAttribute(persist_kernel, cudaFuncAttributeMaxDynamicSharedMemorySize, SMEM_BYTES);

    repack_kernel<<<2 * NT * NT, 256>>>(A);
    init_kernel<<<(LP * 16 + 255) / 256, 256>>>(Bm, theta);
    persist_kernel<<<NT, 320, SMEM_BYTES>>>(xs);   // __cluster_dims__(2,1,1) applies
    mlp_kernel<<<dim3(16, 16), 256>>>(out);
}